// round 5
// baseline (speedup 1.0000x reference)
#include <cuda_runtime.h>
#include <cstdint>
#include <math.h>

#define Bn 8
#define Tn 256
#define Vn 32
#define Dn 256

// ---------------- device scratch (allocation-free) ----------------
__device__ float g_an[Bn * Tn];   // sum_{j!=i,v,k} exp(s) per (i,q)
__device__ float g_ap[Bn * Tn];   // sum_{v,q} exp(s_diag) per (i,k)
__device__ uint8_t g_fb8 [Bn * Tn * Vn * Dn];  // s8 feature      (x64 scaled)
__device__ uint8_t g_fab8[Bn * Tn * Vn * Dn];  // s8 feature_aug  (x64 scaled)

// ---------------- PTX helpers (baseline ISA, sm_80+) ----------------
__device__ __forceinline__ uint32_t smem_to_u32(const void* p) {
    uint32_t a;
    asm("{ .reg .u64 t; cvta.to.shared.u64 t, %1; cvt.u32.u64 %0, t; }"
        : "=r"(a) : "l"(p));
    return a;
}

#define CP_ASYNC16(saddr, gptr) \
    asm volatile("cp.async.cg.shared.global [%0], [%1], 16;" \
        :: "r"(saddr), "l"(gptr))
#define CP_COMMIT() asm volatile("cp.async.commit_group;")
#define CP_WAIT0()  asm volatile("cp.async.wait_group 0;")

#define LDMATRIX_X4(r, addr) \
    asm volatile("ldmatrix.sync.aligned.m8n8.x4.shared.b16 {%0,%1,%2,%3}, [%4];" \
        : "=r"((r)[0]), "=r"((r)[1]), "=r"((r)[2]), "=r"((r)[3]) : "r"(addr))

// int8 MMA: D(4xs32) += A(4xb32: 16x32 s8) * B(2xb32: 32x8 s8)
#define MMA_S8(d, a, b0, b1) \
    asm volatile("mma.sync.aligned.m16n8k32.row.col.s32.s8.s8.s32 " \
        "{%0,%1,%2,%3}, {%4,%5,%6,%7}, {%8,%9}, {%0,%1,%2,%3};" \
        : "+r"((d)[0]), "+r"((d)[1]), "+r"((d)[2]), "+r"((d)[3]) \
        : "r"((a)[0]), "r"((a)[1]), "r"((a)[2]), "r"((a)[3]), "r"(b0), "r"(b1))

// ---------------- layout ----------------
// s8: full K=256 = 256B per row. A tile 128x256B = 32KB, B tile 128x256B = 32KB.
#define A_BYTES 32768
#define B_BYTES 32768
#define SMEM_DYN (A_BYTES + B_BYTES)   // 64 KB -> 2 CTAs/SM

// ---------------- kernels ----------------
__global__ void cvt_kernel(const float* __restrict__ f, const float* __restrict__ fa) {
    int idx = blockIdx.x * blockDim.x + threadIdx.x;
    const int N4 = Bn * Tn * Vn * Dn / 4;
    if (idx < N4) {
        float4 a = ((const float4*)f)[idx];
        float4 b = ((const float4*)fa)[idx];
        int a0 = __float2int_rn(a.x * 64.f), a1 = __float2int_rn(a.y * 64.f);
        int a2 = __float2int_rn(a.z * 64.f), a3 = __float2int_rn(a.w * 64.f);
        int b0 = __float2int_rn(b.x * 64.f), b1 = __float2int_rn(b.y * 64.f);
        int b2 = __float2int_rn(b.z * 64.f), b3 = __float2int_rn(b.w * 64.f);
        ((uint32_t*)g_fb8 )[idx] = (uint32_t)(a0 & 0xff) | ((uint32_t)(a1 & 0xff) << 8)
                                 | ((uint32_t)(a2 & 0xff) << 16) | ((uint32_t)a3 << 24);
        ((uint32_t*)g_fab8)[idx] = (uint32_t)(b0 & 0xff) | ((uint32_t)(b1 & 0xff) << 8)
                                 | ((uint32_t)(b2 & 0xff) << 16) | ((uint32_t)b3 << 24);
    }
    if (idx < Bn * Tn) { g_an[idx] = 0.f; g_ap[idx] = 0.f; }
}

// One CTA: S[128,128] = A[128,256] @ B[128,256]^T (s8, x64 scaled) for one
// (i,j,v,qt,kt); exp(S/4096) + row/col reductions. 8 warps, warp tile 32x64.
__global__ void __launch_bounds__(256, 2) infonce_s8_kernel() {
    extern __shared__ char smem[];
    __shared__ float s_red[128];

    const uint32_t aBase = smem_to_u32(smem);
    const uint32_t bBase = aBase + A_BYTES;
    const int tid  = threadIdx.x;
    const int wid  = tid >> 5;
    const int lane = tid & 31;
    const int warp_m = wid >> 1;   // 0..3 -> m*32
    const int warp_n = wid & 1;    // 0..1 -> n*64

    const int qt = blockIdx.x & 1;
    const int kt = blockIdx.x >> 1;
    const int v  = blockIdx.y;
    const int i  = blockIdx.z >> 3;
    const int j  = blockIdx.z & 7;
    const bool diag = (i == j);

    if (tid < 128) s_red[tid] = 0.f;

    const size_t RS = (size_t)Vn * Dn;  // 8192 bytes between consecutive t
    const uint8_t* Ag = g_fb8  + ((size_t)(i * Tn + qt * 128) * Vn + v) * Dn;
    const uint8_t* Bg = g_fab8 + ((size_t)(j * Tn + kt * 128) * Vn + v) * Dn;

    // ---- load full tiles: 2048 16B chunks each, swizzled rows of 256B ----
    #pragma unroll
    for (int it = 0; it < 8; it++) {
        int id = tid + it * 256;
        int row = id >> 4, c = id & 15;
        uint32_t soff = (uint32_t)(row * 256) + (uint32_t)((c * 16) ^ ((row & 7) << 4));
        CP_ASYNC16(aBase + soff, Ag + (size_t)row * RS + c * 16);
    }
    #pragma unroll
    for (int it = 0; it < 8; it++) {
        int id = tid + it * 256;
        int row = id >> 4, c = id & 15;
        uint32_t soff = (uint32_t)(row * 256) + (uint32_t)((c * 16) ^ ((row & 7) << 4));
        CP_ASYNC16(bBase + soff, Bg + (size_t)row * RS + c * 16);
    }
    CP_COMMIT();

    int32_t acc[2][8][4];
    #pragma unroll
    for (int tm = 0; tm < 2; tm++)
        #pragma unroll
        for (int g = 0; g < 8; g++)
            #pragma unroll
            for (int c = 0; c < 4; c++) acc[tm][g][c] = 0;

    CP_WAIT0();
    __syncthreads();

    // ---- 8 k-steps of 32 s8 each ----
    #pragma unroll
    for (int kk = 0; kk < 8; kk++) {
        uint32_t afr[2][4];
        #pragma unroll
        for (int tm = 0; tm < 2; tm++) {
            int r = warp_m * 32 + tm * 16 + (lane & 7) + ((lane >> 3) & 1) * 8;
            uint32_t kb = (uint32_t)(kk * 32 + ((lane >> 4) & 1) * 16);
            LDMATRIX_X4(afr[tm], aBase + r * 256 + (kb ^ ((r & 7) << 4)));
        }
        #pragma unroll
        for (int gg = 0; gg < 4; gg++) {
            uint32_t bfr[4];
            int n = warp_n * 64 + gg * 16 + (lane & 7) + ((lane >> 4) & 1) * 8;
            uint32_t kb = (uint32_t)(kk * 32 + ((lane >> 3) & 1) * 16);
            LDMATRIX_X4(bfr, bBase + n * 256 + (kb ^ ((n & 7) << 4)));
            #pragma unroll
            for (int tm = 0; tm < 2; tm++) {
                MMA_S8(acc[tm][gg * 2],     afr[tm], bfr[0], bfr[1]);
                MMA_S8(acc[tm][gg * 2 + 1], afr[tm], bfr[2], bfr[3]);
            }
        }
    }

    // ---- epilogue: descale, exp, reductions ----
    // acc[tm][g][c]: row = warp_m*32 + tm*16 + lane/4 + (c>=2 ? 8:0)
    //               col = warp_n*64 + g*8 + (lane&3)*2 + (c&1)
    const float DS = 1.f / 4096.f;   // undo (64x)^2 input scaling

    if (!diag) {
        // negatives: row sums over this CTA's 128 k-cols
        #pragma unroll
        for (int tm = 0; tm < 2; tm++) {
            float rs0 = 0.f, rs1 = 0.f;
            #pragma unroll
            for (int g = 0; g < 8; g++) {
                rs0 += __expf((float)acc[tm][g][0] * DS) + __expf((float)acc[tm][g][1] * DS);
                rs1 += __expf((float)acc[tm][g][2] * DS) + __expf((float)acc[tm][g][3] * DS);
            }
            rs0 += __shfl_xor_sync(0xffffffffu, rs0, 1);
            rs0 += __shfl_xor_sync(0xffffffffu, rs0, 2);
            rs1 += __shfl_xor_sync(0xffffffffu, rs1, 1);
            rs1 += __shfl_xor_sync(0xffffffffu, rs1, 2);
            if ((lane & 3) == 0) {
                int r = warp_m * 32 + tm * 16 + (lane >> 2);
                atomicAdd(&s_red[r], rs0);
                atomicAdd(&s_red[r + 8], rs1);
            }
        }
        __syncthreads();
        if (tid < 128) atomicAdd(&g_an[i * Tn + qt * 128 + tid], s_red[tid]);
    } else {
        // positives: col sums over this CTA's 128 q-rows
        #pragma unroll
        for (int g = 0; g < 8; g++) {
            float cs0 = __expf((float)acc[0][g][0] * DS) + __expf((float)acc[0][g][2] * DS)
                      + __expf((float)acc[1][g][0] * DS) + __expf((float)acc[1][g][2] * DS);
            float cs1 = __expf((float)acc[0][g][1] * DS) + __expf((float)acc[0][g][3] * DS)
                      + __expf((float)acc[1][g][1] * DS) + __expf((float)acc[1][g][3] * DS);
            cs0 += __shfl_xor_sync(0xffffffffu, cs0, 4);
            cs0 += __shfl_xor_sync(0xffffffffu, cs0, 8);
            cs0 += __shfl_xor_sync(0xffffffffu, cs0, 16);
            cs1 += __shfl_xor_sync(0xffffffffu, cs1, 4);
            cs1 += __shfl_xor_sync(0xffffffffu, cs1, 8);
            cs1 += __shfl_xor_sync(0xffffffffu, cs1, 16);
            if (lane < 4) {
                int c = warp_n * 64 + g * 8 + lane * 2;
                atomicAdd(&s_red[c], cs0);
                atomicAdd(&s_red[c + 1], cs1);
            }
        }
        __syncthreads();
        if (tid < 128) atomicAdd(&g_ap[i * Tn + kt * 128 + tid], s_red[tid]);
    }
}

__global__ void loss_kernel(float* out) {
    __shared__ float red[256];
    int tid = threadIdx.x;
    float s = 0.f;
    for (int idx = tid; idx < Bn * Tn; idx += 256)
        s += logf(g_an[idx]) - logf(g_ap[idx]);
    red[tid] = s;
    __syncthreads();
    for (int m = 128; m > 0; m >>= 1) {
        if (tid < m) red[tid] += red[tid + m];
        __syncthreads();
    }
    if (tid == 0) out[0] = red[0] / (float)Tn;
}

// ---------------- launch ----------------
extern "C" void kernel_launch(void* const* d_in, const int* in_sizes, int n_in,
                              void* d_out, int out_size) {
    const float* f  = (const float*)d_in[0];   // feature     [B,T,V,D]
    const float* fa = (const float*)d_in[1];   // feature_aug [B,T,V,D]

    cvt_kernel<<<(Bn * Tn * Vn * Dn / 4 + 255) / 256, 256>>>(f, fa);

    cudaFuncSetAttribute(infonce_s8_kernel,
                         cudaFuncAttributeMaxDynamicSharedMemorySize, SMEM_DYN);
    dim3 grid(4, Vn, Bn * Bn);   // (qt + 2*kt, v, i*8+j)
    infonce_s8_kernel<<<grid, 256, SMEM_DYN>>>();

    loss_kernel<<<1, 256>>>((float*)d_out);
}

// round 6
// speedup vs baseline: 2.1311x; 2.1311x over previous
#include <cuda_runtime.h>
#include <cuda_fp8.h>
#include <cstdint>
#include <math.h>

#define Bn 8
#define Tn 256
#define Vn 32
#define Dn 256
#define NTILES 8192        // 2 qt * 2 kt * 32 v * 64 ij
#define GRID_P 304         // 152 SMs * 2 CTAs

// ---------------- device scratch (allocation-free) ----------------
__device__ float g_an[Bn * Tn];
__device__ float g_ap[Bn * Tn];
__device__ uint8_t g_fb8 [Bn * Tn * Vn * Dn];  // e4m3 feature      (x32)
__device__ uint8_t g_fab8[Bn * Tn * Vn * Dn];  // e4m3 feature_aug  (x32)

// ---------------- PTX helpers (baseline ISA) ----------------
__device__ __forceinline__ uint32_t smem_to_u32(const void* p) {
    uint32_t a;
    asm("{ .reg .u64 t; cvta.to.shared.u64 t, %1; cvt.u32.u64 %0, t; }"
        : "=r"(a) : "l"(p));
    return a;
}
#define CP_ASYNC16(saddr, gptr) \
    asm volatile("cp.async.cg.shared.global [%0], [%1], 16;" :: "r"(saddr), "l"(gptr))
#define CP_COMMIT() asm volatile("cp.async.commit_group;")
#define CP_WAIT0()  asm volatile("cp.async.wait_group 0;")
#define LDMATRIX_X4(r, addr) \
    asm volatile("ldmatrix.sync.aligned.m8n8.x4.shared.b16 {%0,%1,%2,%3}, [%4];" \
        : "=r"((r)[0]), "=r"((r)[1]), "=r"((r)[2]), "=r"((r)[3]) : "r"(addr))
#define MMA_FP8(d, a, b0, b1) \
    asm volatile("mma.sync.aligned.m16n8k32.row.col.f32.e4m3.e4m3.f32 " \
        "{%0,%1,%2,%3}, {%4,%5,%6,%7}, {%8,%9}, {%0,%1,%2,%3};" \
        : "+f"((d)[0]), "+f"((d)[1]), "+f"((d)[2]), "+f"((d)[3]) \
        : "r"((a)[0]), "r"((a)[1]), "r"((a)[2]), "r"((a)[3]), "r"(b0), "r"(b1))

// ---------------- layout ----------------
// half-K chunk: A 128x128B (16KB) + B 128x128B (16KB) = 32KB per stage, 2 stages
#define HALF_A 16384
#define STAGE  32768
#define SMEM_DYN (2 * STAGE)    // 64 KB -> occ 2

// tile decode: t = qt | kt<<1 | v<<2 | (i*8+j)<<7
struct TileIdx { int qt, kt, v, i, j; };
__device__ __forceinline__ TileIdx decode(int t) {
    TileIdx x;
    x.qt = t & 1; x.kt = (t >> 1) & 1; x.v = (t >> 2) & 31;
    int ij = t >> 7; x.i = ij >> 3; x.j = ij & 7;
    return x;
}

// ---------------- kernels ----------------
__global__ void cvt_kernel(const float* __restrict__ f, const float* __restrict__ fa) {
    int idx = blockIdx.x * blockDim.x + threadIdx.x;
    const int N4 = Bn * Tn * Vn * Dn / 4;
    if (idx < N4) {
        float4 a = ((const float4*)f)[idx];
        float4 b = ((const float4*)fa)[idx];
        a.x *= 32.f; a.y *= 32.f; a.z *= 32.f; a.w *= 32.f;
        b.x *= 32.f; b.y *= 32.f; b.z *= 32.f; b.w *= 32.f;
        ((uint32_t*)g_fb8 )[idx] = __nv_fp8x4_e4m3(a).__x;
        ((uint32_t*)g_fab8)[idx] = __nv_fp8x4_e4m3(b).__x;
    }
    if (idx < Bn * Tn) { g_an[idx] = 0.f; g_ap[idx] = 0.f; }
}

// prefetch one half-K chunk (h*128..h*128+127 of D) of tile t into stage at dst
__device__ __forceinline__ void prefetch_half(int t, int h, uint32_t dst, int tid) {
    TileIdx x = decode(t);
    const size_t RS = (size_t)Vn * Dn;
    const uint8_t* Ag = g_fb8  + ((size_t)(x.i * Tn + x.qt * 128) * Vn + x.v) * Dn + h * 128;
    const uint8_t* Bg = g_fab8 + ((size_t)(x.j * Tn + x.kt * 128) * Vn + x.v) * Dn + h * 128;
    #pragma unroll
    for (int it = 0; it < 4; it++) {            // A half: 1024 16B chunks
        int id = tid + it * 256;
        int row = id >> 3, c = id & 7;
        uint32_t soff = (uint32_t)(row * 128) + (uint32_t)((c * 16) ^ ((row & 7) << 4));
        CP_ASYNC16(dst + soff, Ag + (size_t)row * RS + c * 16);
    }
    #pragma unroll
    for (int it = 0; it < 4; it++) {            // B half
        int id = tid + it * 256;
        int row = id >> 3, c = id & 7;
        uint32_t soff = (uint32_t)(row * 128) + (uint32_t)((c * 16) ^ ((row & 7) << 4));
        CP_ASYNC16(dst + HALF_A + soff, Bg + (size_t)row * RS + c * 16);
    }
}

// Persistent: each CTA loops over tiles t = bid, bid+G, ...
// Per tile: S[128,128] = A[128,256] @ B[128,256]^T (fp8 x32), exp(S/1024), reduce.
__global__ void __launch_bounds__(256, 2) infonce_fp8_persist() {
    extern __shared__ char smem[];
    __shared__ float s_red[128];

    const uint32_t base = smem_to_u32(smem);
    const int tid  = threadIdx.x;
    const int wid  = tid >> 5;
    const int lane = tid & 31;
    const int warp_m = wid >> 1;   // 0..3 -> m*32
    const int warp_n = wid & 1;    // 0..1 -> n*64
    const int G = gridDim.x;

    int t = blockIdx.x;
    int buf = 0;
    if (t < NTILES) { prefetch_half(t, 0, base, tid); CP_COMMIT(); }

    while (t < NTILES) {
        float acc[2][8][4];
        #pragma unroll
        for (int tm = 0; tm < 2; tm++)
            #pragma unroll
            for (int g = 0; g < 8; g++)
                #pragma unroll
                for (int c = 0; c < 4; c++) acc[tm][g][c] = 0.f;

        #pragma unroll
        for (int h = 0; h < 2; h++) {
            CP_WAIT0();
            __syncthreads();
            // issue next chunk into the other stage
            if (h == 0) {
                prefetch_half(t, 1, base + (buf ^ 1) * STAGE, tid);
                CP_COMMIT();
                if (tid < 128) s_red[tid] = 0.f;
            } else {
                int tn = t + G;
                if (tn < NTILES) {
                    prefetch_half(tn, 0, base + (buf ^ 1) * STAGE, tid);
                    CP_COMMIT();
                }
            }
            // compute 4 k-steps from current stage
            const uint32_t aB = base + buf * STAGE;
            const uint32_t bB = aB + HALF_A;
            #pragma unroll
            for (int kk = 0; kk < 4; kk++) {
                uint32_t afr[2][4];
                #pragma unroll
                for (int tm = 0; tm < 2; tm++) {
                    int r = warp_m * 32 + tm * 16 + (lane & 7) + ((lane >> 3) & 1) * 8;
                    uint32_t kb = (uint32_t)(kk * 32 + ((lane >> 4) & 1) * 16);
                    LDMATRIX_X4(afr[tm], aB + r * 128 + (kb ^ ((r & 7) << 4)));
                }
                #pragma unroll
                for (int gg = 0; gg < 4; gg++) {
                    uint32_t bfr[4];
                    int n = warp_n * 64 + gg * 16 + (lane & 7) + ((lane >> 4) & 1) * 8;
                    uint32_t kb = (uint32_t)(kk * 32 + ((lane >> 3) & 1) * 16);
                    LDMATRIX_X4(bfr, bB + n * 128 + (kb ^ ((n & 7) << 4)));
                    #pragma unroll
                    for (int tm = 0; tm < 2; tm++) {
                        MMA_FP8(acc[tm][gg * 2],     afr[tm], bfr[0], bfr[1]);
                        MMA_FP8(acc[tm][gg * 2 + 1], afr[tm], bfr[2], bfr[3]);
                    }
                }
            }
            buf ^= 1;
        }

        // ---- epilogue: descale, exp, reduce (overlaps next tile's chunk0 load) ----
        TileIdx x = decode(t);
        const bool diag = (x.i == x.j);
        const float DS = 1.f / 1024.f;

        if (!diag) {
            #pragma unroll
            for (int tm = 0; tm < 2; tm++) {
                float rs0 = 0.f, rs1 = 0.f;
                #pragma unroll
                for (int g = 0; g < 8; g++) {
                    rs0 += __expf(acc[tm][g][0] * DS) + __expf(acc[tm][g][1] * DS);
                    rs1 += __expf(acc[tm][g][2] * DS) + __expf(acc[tm][g][3] * DS);
                }
                rs0 += __shfl_xor_sync(0xffffffffu, rs0, 1);
                rs0 += __shfl_xor_sync(0xffffffffu, rs0, 2);
                rs1 += __shfl_xor_sync(0xffffffffu, rs1, 1);
                rs1 += __shfl_xor_sync(0xffffffffu, rs1, 2);
                if ((lane & 3) == 0) {
                    int r = warp_m * 32 + tm * 16 + (lane >> 2);
                    atomicAdd(&s_red[r], rs0);
                    atomicAdd(&s_red[r + 8], rs1);
                }
            }
            __syncthreads();
            if (tid < 128) atomicAdd(&g_an[x.i * Tn + x.qt * 128 + tid], s_red[tid]);
        } else {
            #pragma unroll
            for (int g = 0; g < 8; g++) {
                float cs0 = __expf(acc[0][g][0] * DS) + __expf(acc[0][g][2] * DS)
                          + __expf(acc[1][g][0] * DS) + __expf(acc[1][g][2] * DS);
                float cs1 = __expf(acc[0][g][1] * DS) + __expf(acc[0][g][3] * DS)
                          + __expf(acc[1][g][1] * DS) + __expf(acc[1][g][3] * DS);
                cs0 += __shfl_xor_sync(0xffffffffu, cs0, 4);
                cs0 += __shfl_xor_sync(0xffffffffu, cs0, 8);
                cs0 += __shfl_xor_sync(0xffffffffu, cs0, 16);
                cs1 += __shfl_xor_sync(0xffffffffu, cs1, 4);
                cs1 += __shfl_xor_sync(0xffffffffu, cs1, 8);
                cs1 += __shfl_xor_sync(0xffffffffu, cs1, 16);
                if (lane < 4) {
                    int c = warp_n * 64 + g * 8 + lane * 2;
                    atomicAdd(&s_red[c], cs0);
                    atomicAdd(&s_red[c + 1], cs1);
                }
            }
            __syncthreads();
            if (tid < 128) atomicAdd(&g_ap[x.i * Tn + x.kt * 128 + tid], s_red[tid]);
        }

        t += G;
    }
}

__global__ void loss_kernel(float* out) {
    __shared__ float red[256];
    int tid = threadIdx.x;
    float s = 0.f;
    for (int idx = tid; idx < Bn * Tn; idx += 256)
        s += logf(g_an[idx]) - logf(g_ap[idx]);
    red[tid] = s;
    __syncthreads();
    for (int m = 128; m > 0; m >>= 1) {
        if (tid < m) red[tid] += red[tid + m];
        __syncthreads();
    }
    if (tid == 0) out[0] = red[0] / (float)Tn;
}

// ---------------- launch ----------------
extern "C" void kernel_launch(void* const* d_in, const int* in_sizes, int n_in,
                              void* d_out, int out_size) {
    const float* f  = (const float*)d_in[0];
    const float* fa = (const float*)d_in[1];

    cvt_kernel<<<(Bn * Tn * Vn * Dn / 4 + 255) / 256, 256>>>(f, fa);

    cudaFuncSetAttribute(infonce_fp8_persist,
                         cudaFuncAttributeMaxDynamicSharedMemorySize, SMEM_DYN);
    infonce_fp8_persist<<<GRID_P, 256, SMEM_DYN>>>();

    loss_kernel<<<1, 256>>>((float*)d_out);
}

// round 7
// speedup vs baseline: 2.3169x; 1.0872x over previous
#include <cuda_runtime.h>
#include <cuda_fp8.h>
#include <cuda_fp16.h>
#include <cstdint>
#include <math.h>

#define Bn 8
#define Tn 256
#define Vn 32
#define Dn 256

// ---------------- device scratch (allocation-free) ----------------
__device__ float g_an[Bn * Tn];   // sum_{j!=i,v,k} exp(s) per (i,q)
__device__ float g_ap[Bn * Tn];   // sum_{v,q} exp(s_diag) per (i,k)
__device__ uint8_t g_fb8 [Bn * Tn * Vn * Dn];  // e4m3 feature      (x32 scaled)
__device__ uint8_t g_fab8[Bn * Tn * Vn * Dn];  // e4m3 feature_aug  (x32 scaled)

// ---------------- PTX helpers (baseline ISA, sm_89/90 features) ----------------
__device__ __forceinline__ uint32_t smem_to_u32(const void* p) {
    uint32_t a;
    asm("{ .reg .u64 t; cvta.to.shared.u64 t, %1; cvt.u32.u64 %0, t; }"
        : "=r"(a) : "l"(p));
    return a;
}

#define CP_ASYNC16(saddr, gptr) \
    asm volatile("cp.async.cg.shared.global [%0], [%1], 16;" \
        :: "r"(saddr), "l"(gptr))
#define CP_COMMIT() asm volatile("cp.async.commit_group;")
#define CP_WAIT0()  asm volatile("cp.async.wait_group 0;")

#define LDMATRIX_X4(r, addr) \
    asm volatile("ldmatrix.sync.aligned.m8n8.x4.shared.b16 {%0,%1,%2,%3}, [%4];" \
        : "=r"((r)[0]), "=r"((r)[1]), "=r"((r)[2]), "=r"((r)[3]) : "r"(addr))

// fp8 e4m3 MMA with FP16 accumulator: D(2xb32 = 4xf16) += A * B
#define MMA_FP8_F16(d, a, b0, b1) \
    asm volatile("mma.sync.aligned.m16n8k32.row.col.f16.e4m3.e4m3.f16 " \
        "{%0,%1}, {%2,%3,%4,%5}, {%6,%7}, {%0,%1};" \
        : "+r"((d)[0]), "+r"((d)[1]) \
        : "r"((a)[0]), "r"((a)[1]), "r"((a)[2]), "r"((a)[3]), "r"(b0), "r"(b1))

// ---------------- layout ----------------
// fp8: full K=256 = 256B per row. A tile 128x256B = 32KB, B tile 128x256B = 32KB.
#define A_BYTES 32768
#define B_BYTES 32768
#define SMEM_DYN (A_BYTES + B_BYTES)   // 64 KB -> 2 CTAs/SM

// ---------------- kernels ----------------
__global__ void cvt_kernel(const float* __restrict__ f, const float* __restrict__ fa) {
    int idx = blockIdx.x * blockDim.x + threadIdx.x;
    const int N4 = Bn * Tn * Vn * Dn / 4;
    if (idx < N4) {
        float4 a = ((const float4*)f)[idx];
        float4 b = ((const float4*)fa)[idx];
        a.x *= 32.f; a.y *= 32.f; a.z *= 32.f; a.w *= 32.f;
        b.x *= 32.f; b.y *= 32.f; b.z *= 32.f; b.w *= 32.f;
        ((uint32_t*)g_fb8 )[idx] = __nv_fp8x4_e4m3(a).__x;
        ((uint32_t*)g_fab8)[idx] = __nv_fp8x4_e4m3(b).__x;
    }
    if (idx < Bn * Tn) { g_an[idx] = 0.f; g_ap[idx] = 0.f; }
}

// One CTA: S[128,128] = A[128,256] @ B[128,256]^T (fp8 x32, f16 accum) for one
// (i,j,v,qt,kt); exp(S/1024) + row/col reductions. 8 warps, warp tile 32x64.
__global__ void __launch_bounds__(256, 2) infonce_fp8h_kernel() {
    extern __shared__ char smem[];
    __shared__ float s_red[128];

    const uint32_t aBase = smem_to_u32(smem);
    const uint32_t bBase = aBase + A_BYTES;
    const int tid  = threadIdx.x;
    const int wid  = tid >> 5;
    const int lane = tid & 31;
    const int warp_m = wid >> 1;   // 0..3 -> m*32
    const int warp_n = wid & 1;    // 0..1 -> n*64

    const int qt = blockIdx.x & 1;
    const int kt = blockIdx.x >> 1;
    const int v  = blockIdx.y;
    const int i  = blockIdx.z >> 3;
    const int j  = blockIdx.z & 7;
    const bool diag = (i == j);

    if (tid < 128) s_red[tid] = 0.f;

    const size_t RS = (size_t)Vn * Dn;  // 8192 bytes between consecutive t
    const uint8_t* Ag = g_fb8  + ((size_t)(i * Tn + qt * 128) * Vn + v) * Dn;
    const uint8_t* Bg = g_fab8 + ((size_t)(j * Tn + kt * 128) * Vn + v) * Dn;

    // ---- load full tiles: 2048 16B chunks each, swizzled rows of 256B ----
    #pragma unroll
    for (int it = 0; it < 8; it++) {
        int id = tid + it * 256;
        int row = id >> 4, c = id & 15;
        uint32_t soff = (uint32_t)(row * 256) + (uint32_t)((c * 16) ^ ((row & 7) << 4));
        CP_ASYNC16(aBase + soff, Ag + (size_t)row * RS + c * 16);
    }
    #pragma unroll
    for (int it = 0; it < 8; it++) {
        int id = tid + it * 256;
        int row = id >> 4, c = id & 15;
        uint32_t soff = (uint32_t)(row * 256) + (uint32_t)((c * 16) ^ ((row & 7) << 4));
        CP_ASYNC16(bBase + soff, Bg + (size_t)row * RS + c * 16);
    }
    CP_COMMIT();

    // f16 accumulators: [tm][g][2 b32] = 4 halves each
    uint32_t acc[2][8][2];
    #pragma unroll
    for (int tm = 0; tm < 2; tm++)
        #pragma unroll
        for (int g = 0; g < 8; g++) {
            acc[tm][g][0] = 0u; acc[tm][g][1] = 0u;
        }

    CP_WAIT0();
    __syncthreads();

    // ---- 8 k-steps of 32 fp8 each ----
    #pragma unroll
    for (int kk = 0; kk < 8; kk++) {
        uint32_t afr[2][4];
        #pragma unroll
        for (int tm = 0; tm < 2; tm++) {
            int r = warp_m * 32 + tm * 16 + (lane & 7) + ((lane >> 3) & 1) * 8;
            uint32_t kb = (uint32_t)(kk * 32 + ((lane >> 4) & 1) * 16);
            LDMATRIX_X4(afr[tm], aBase + r * 256 + (kb ^ ((r & 7) << 4)));
        }
        #pragma unroll
        for (int gg = 0; gg < 4; gg++) {
            uint32_t bfr[4];
            int n = warp_n * 64 + gg * 16 + (lane & 7) + ((lane >> 4) & 1) * 8;
            uint32_t kb = (uint32_t)(kk * 32 + ((lane >> 3) & 1) * 16);
            LDMATRIX_X4(bfr, bBase + n * 256 + (kb ^ ((n & 7) << 4)));
            #pragma unroll
            for (int tm = 0; tm < 2; tm++) {
                MMA_FP8_F16(acc[tm][gg * 2],     afr[tm], bfr[0], bfr[1]);
                MMA_FP8_F16(acc[tm][gg * 2 + 1], afr[tm], bfr[2], bfr[3]);
            }
        }
    }

    // ---- epilogue: unpack f16, descale, exp, reductions ----
    // acc[tm][g]: reg0 = halves (c0,c1) @ row r0 = warp_m*32+tm*16+lane/4
    //             reg1 = halves (c2,c3) @ row r1 = r0+8
    //             cols c0 = warp_n*64+g*8+(lane&3)*2, c1 = c0+1
    const float DS = 1.f / 1024.f;   // undo (32x)^2 input scaling

    if (!diag) {
        // negatives: row sums over this CTA's 128 k-cols
        #pragma unroll
        for (int tm = 0; tm < 2; tm++) {
            float rs0 = 0.f, rs1 = 0.f;
            #pragma unroll
            for (int g = 0; g < 8; g++) {
                float2 e0 = __half22float2(*(const __half2*)&acc[tm][g][0]);
                float2 e1 = __half22float2(*(const __half2*)&acc[tm][g][1]);
                rs0 += __expf(e0.x * DS) + __expf(e0.y * DS);
                rs1 += __expf(e1.x * DS) + __expf(e1.y * DS);
            }
            rs0 += __shfl_xor_sync(0xffffffffu, rs0, 1);
            rs0 += __shfl_xor_sync(0xffffffffu, rs0, 2);
            rs1 += __shfl_xor_sync(0xffffffffu, rs1, 1);
            rs1 += __shfl_xor_sync(0xffffffffu, rs1, 2);
            if ((lane & 3) == 0) {
                int r = warp_m * 32 + tm * 16 + (lane >> 2);
                atomicAdd(&s_red[r], rs0);
                atomicAdd(&s_red[r + 8], rs1);
            }
        }
        __syncthreads();
        if (tid < 128) atomicAdd(&g_an[i * Tn + qt * 128 + tid], s_red[tid]);
    } else {
        // positives: col sums over this CTA's 128 q-rows
        #pragma unroll
        for (int g = 0; g < 8; g++) {
            float2 a00 = __half22float2(*(const __half2*)&acc[0][g][0]);
            float2 a01 = __half22float2(*(const __half2*)&acc[0][g][1]);
            float2 a10 = __half22float2(*(const __half2*)&acc[1][g][0]);
            float2 a11 = __half22float2(*(const __half2*)&acc[1][g][1]);
            float cs0 = __expf(a00.x * DS) + __expf(a01.x * DS)
                      + __expf(a10.x * DS) + __expf(a11.x * DS);
            float cs1 = __expf(a00.y * DS) + __expf(a01.y * DS)
                      + __expf(a10.y * DS) + __expf(a11.y * DS);
            cs0 += __shfl_xor_sync(0xffffffffu, cs0, 4);
            cs0 += __shfl_xor_sync(0xffffffffu, cs0, 8);
            cs0 += __shfl_xor_sync(0xffffffffu, cs0, 16);
            cs1 += __shfl_xor_sync(0xffffffffu, cs1, 4);
            cs1 += __shfl_xor_sync(0xffffffffu, cs1, 8);
            cs1 += __shfl_xor_sync(0xffffffffu, cs1, 16);
            if (lane < 4) {
                int c = warp_n * 64 + g * 8 + lane * 2;
                atomicAdd(&s_red[c], cs0);
                atomicAdd(&s_red[c + 1], cs1);
            }
        }
        __syncthreads();
        if (tid < 128) atomicAdd(&g_ap[i * Tn + kt * 128 + tid], s_red[tid]);
    }
}

__global__ void loss_kernel(float* out) {
    __shared__ float red[256];
    int tid = threadIdx.x;
    float s = 0.f;
    for (int idx = tid; idx < Bn * Tn; idx += 256)
        s += logf(g_an[idx]) - logf(g_ap[idx]);
    red[tid] = s;
    __syncthreads();
    for (int m = 128; m > 0; m >>= 1) {
        if (tid < m) red[tid] += red[tid + m];
        __syncthreads();
    }
    if (tid == 0) out[0] = red[0] / (float)Tn;
}

// ---------------- launch ----------------
extern "C" void kernel_launch(void* const* d_in, const int* in_sizes, int n_in,
                              void* d_out, int out_size) {
    const float* f  = (const float*)d_in[0];   // feature     [B,T,V,D]
    const float* fa = (const float*)d_in[1];   // feature_aug [B,T,V,D]

    cvt_kernel<<<(Bn * Tn * Vn * Dn / 4 + 255) / 256, 256>>>(f, fa);

    cudaFuncSetAttribute(infonce_fp8h_kernel,
                         cudaFuncAttributeMaxDynamicSharedMemorySize, SMEM_DYN);
    dim3 grid(4, Vn, Bn * Bn);   // (qt + 2*kt, v, i*8+j)
    infonce_fp8h_kernel<<<grid, 256, SMEM_DYN>>>();

    loss_kernel<<<1, 256>>>((float*)d_out);
}